// round 1
// baseline (speedup 1.0000x reference)
#include <cuda_runtime.h>
#include <cstdint>

#define NREPO 30000
#define NUSER 70000
#define NNODE 100000
#define RREL  8
#define HDIM  128

// ---------------- scratch (static device globals; allocation-free) ----------
__device__ float g_h0[(size_t)NNODE * HDIM];            // 51.2 MB
__device__ float g_h1[(size_t)NNODE * HDIM];            // 51.2 MB
__device__ float g_y1[(size_t)NREPO * RREL * HDIM];     // 122.9 MB
__device__ float g_sum2[(size_t)NREPO * RREL * HDIM];   // 122.9 MB
__device__ float g_out2[(size_t)NREPO * HDIM];          // 15.4 MB
__device__ int   g_cnt1[NUSER * RREL];
__device__ int   g_cnt2[NREPO * RREL];

// ---------------- small kernels ---------------------------------------------
__global__ void zero_all_k() {
    size_t i = (size_t)blockIdx.x * blockDim.x + threadIdx.x;
    if (i < (size_t)NUSER * RREL) g_cnt1[i] = 0;
    if (i < (size_t)NREPO * RREL) g_cnt2[i] = 0;
    if (i < (size_t)NREPO * RREL * HDIM) g_sum2[i] = 0.f;
}

__global__ void count_k(const int* __restrict__ er, const int* __restrict__ ea,
                        const int* __restrict__ et, int E) {
    int e = blockIdx.x * blockDim.x + threadIdx.x;
    if (e >= E) return;
    atomicAdd(&g_cnt1[ea[e] * RREL + et[e]], 1);
    atomicAdd(&g_cnt2[er[e] * RREL + et[e]], 1);
}

__global__ void mlp_k(const float* __restrict__ x, const float* __restrict__ w,
                      const float* __restrict__ b) {
    int g = blockIdx.x * blockDim.x + threadIdx.x;
    if (g >= NNODE * HDIM) return;
    int n = g >> 7, o = g & 127;
    float acc = b[o];
#pragma unroll
    for (int k = 0; k < 8; k++) acc = fmaf(__ldg(&x[n * 8 + k]), __ldg(&w[k * HDIM + o]), acc);
    g_h0[g] = fmaxf(acc, 0.f);
}

// vectorized fp32 reduction (sm_90+)
__device__ __forceinline__ void red_add_v4(float* p, float a, float b, float c, float d) {
    asm volatile("red.global.add.v4.f32 [%0], {%1,%2,%3,%4};"
                 :: "l"(p), "f"(a), "f"(b), "f"(c), "f"(d) : "memory");
}

// layer-1 scatter: one warp per edge; h1[actor] += y1[repo,etype] / cnt1[actor,etype]
__global__ void scatter1_k(const int* __restrict__ er, const int* __restrict__ ea,
                           const int* __restrict__ et, int E) {
    int idx  = blockIdx.x * blockDim.x + threadIdx.x;
    int e    = idx >> 5;
    int lane = idx & 31;
    if (e >= E) return;
    int repo = __ldg(er + e), actor = __ldg(ea + e), t = __ldg(et + e);
    float inv = 1.0f / (float)max(g_cnt1[actor * RREL + t], 1);
    const float4 v = *(const float4*)(g_y1 + (((size_t)repo * RREL + t) << 7) + lane * 4);
    float* dst = g_h1 + (((size_t)(NREPO + actor)) << 7) + lane * 4;
    red_add_v4(dst, v.x * inv, v.y * inv, v.z * inv, v.w * inv);
}

__global__ void finalize1_k(const float* __restrict__ b1) {
    int g = blockIdx.x * blockDim.x + threadIdx.x;
    if (g >= NNODE * HDIM) return;
    g_h1[g] = fmaxf(g_h1[g] + b1[g & 127], 0.f);
}

// layer-2 scatter: sum2[repo,etype] += h1[actor]
__global__ void scatter2_k(const int* __restrict__ er, const int* __restrict__ ea,
                           const int* __restrict__ et, int E) {
    int idx  = blockIdx.x * blockDim.x + threadIdx.x;
    int e    = idx >> 5;
    int lane = idx & 31;
    if (e >= E) return;
    int repo = __ldg(er + e), actor = __ldg(ea + e), t = __ldg(et + e);
    const float4 v = *(const float4*)(g_h1 + (((size_t)(NREPO + actor)) << 7) + lane * 4);
    float* dst = g_sum2 + (((size_t)repo * RREL + t) << 7) + lane * 4;
    red_add_v4(dst, v.x, v.y, v.z, v.w);
}

__global__ void scale2_k() {
    size_t i = (size_t)blockIdx.x * blockDim.x + threadIdx.x;
    if (i >= (size_t)NREPO * RREL * HDIM) return;
    int row = (int)(i >> 7);
    float inv = 1.0f / (float)max(g_cnt2[row], 1);
    g_sum2[i] *= inv;
}

// finalize layer 2 + classifier: one 128-thread block per repo
__global__ void fincls_k(const float* __restrict__ b2, const float* __restrict__ clsw,
                         const float* __restrict__ clsb, float* __restrict__ out) {
    int j = blockIdx.x;
    int t = threadIdx.x;
    float v = fmaxf(g_out2[(size_t)j * HDIM + t] + b2[t], 0.f);
    float p0 = v * clsw[t * 2 + 0];
    float p1 = v * clsw[t * 2 + 1];
#pragma unroll
    for (int o = 16; o; o >>= 1) {
        p0 += __shfl_xor_sync(0xffffffffu, p0, o);
        p1 += __shfl_xor_sync(0xffffffffu, p1, o);
    }
    __shared__ float s0[4], s1[4];
    if ((t & 31) == 0) { s0[t >> 5] = p0; s1[t >> 5] = p1; }
    __syncthreads();
    if (t == 0) {
        out[j * 2 + 0] = s0[0] + s0[1] + s0[2] + s0[3] + clsb[0];
        out[j * 2 + 1] = s1[0] + s1[1] + s1[2] + s1[3] + clsb[1];
    }
}

// ---------------- SGEMM: C[M x 128] (+)= A[M x K] @ B[K x 128] --------------
// blockIdx.z selects B matrix (B += z*bStrideZ) and C column offset (z*cOffZ).
// A row stride == K. C row stride = cstride. beta: 0 = overwrite, 1 = add.
#define TM 128
#define TN 128
#define TK 16

__global__ void __launch_bounds__(256)
sgemm_k(const float* __restrict__ A, int M, int K,
        const float* __restrict__ B, long bStrideZ,
        float* __restrict__ C, int cstride, int cOffZ, int beta) {
    __shared__ float As[2][TK][TM];
    __shared__ float Bs[2][TK][TN];

    int z = blockIdx.z;
    B += (size_t)z * bStrideZ;
    int cOff = z * cOffZ;
    int m0 = blockIdx.x * TM;
    int tid = threadIdx.x;
    int tx = tid & 15, ty = tid >> 4;

    float acc[8][8];
#pragma unroll
    for (int i = 0; i < 8; i++)
#pragma unroll
        for (int j = 0; j < 8; j++) acc[i][j] = 0.f;

    auto loadA = [&](int k0, int buf) {
#pragma unroll
        for (int i = 0; i < 2; i++) {
            int q = tid + i * 256;        // 0..511
            int row = q >> 2;             // 0..127
            int kq = (q & 3) * 4;         // 0,4,8,12
            float4 v = make_float4(0.f, 0.f, 0.f, 0.f);
            int gm = m0 + row;
            if (gm < M) v = *(const float4*)(A + (size_t)gm * K + k0 + kq);
            As[buf][kq + 0][row] = v.x;
            As[buf][kq + 1][row] = v.y;
            As[buf][kq + 2][row] = v.z;
            As[buf][kq + 3][row] = v.w;
        }
    };
    auto loadB = [&](int k0, int buf) {
#pragma unroll
        for (int i = 0; i < 2; i++) {
            int q = tid + i * 256;
            int kk = q >> 5;              // 0..15
            int n4 = (q & 31) * 4;        // 0..124
            float4 v = *(const float4*)(B + (size_t)(k0 + kk) * TN + n4);
            *(float4*)&Bs[buf][kk][n4] = v;
        }
    };

    loadA(0, 0);
    loadB(0, 0);
    __syncthreads();
    int nk = K / TK;
    for (int kt = 0; kt < nk; kt++) {
        int buf = kt & 1;
        if (kt + 1 < nk) { loadA((kt + 1) * TK, buf ^ 1); loadB((kt + 1) * TK, buf ^ 1); }
#pragma unroll
        for (int kk = 0; kk < TK; kk++) {
            float a[8], b[8];
            *(float4*)&a[0] = *(const float4*)&As[buf][kk][ty * 8];
            *(float4*)&a[4] = *(const float4*)&As[buf][kk][ty * 8 + 4];
            *(float4*)&b[0] = *(const float4*)&Bs[buf][kk][tx * 8];
            *(float4*)&b[4] = *(const float4*)&Bs[buf][kk][tx * 8 + 4];
#pragma unroll
            for (int i = 0; i < 8; i++)
#pragma unroll
                for (int j = 0; j < 8; j++) acc[i][j] = fmaf(a[i], b[j], acc[i][j]);
        }
        __syncthreads();
    }

#pragma unroll
    for (int i = 0; i < 8; i++) {
        int gm = m0 + ty * 8 + i;
        if (gm >= M) continue;
        float* crow = C + (size_t)gm * cstride + cOff + tx * 8;
        if (beta) {
#pragma unroll
            for (int j = 0; j < 8; j++) crow[j] += acc[i][j];
        } else {
#pragma unroll
            for (int j = 0; j < 8; j++) crow[j] = acc[i][j];
        }
    }
}

// ---------------- driver -----------------------------------------------------
extern "C" void kernel_launch(void* const* d_in, const int* in_sizes, int n_in,
                              void* d_out, int out_size) {
    const float* x     = (const float*)d_in[0];
    const int*   er    = (const int*)d_in[1];
    const int*   ea    = (const int*)d_in[2];
    const int*   et    = (const int*)d_in[3];
    const float* mlp_w = (const float*)d_in[4];
    const float* mlp_b = (const float*)d_in[5];
    const float* w1    = (const float*)d_in[6];
    const float* root1 = (const float*)d_in[7];
    const float* b1    = (const float*)d_in[8];
    const float* w2    = (const float*)d_in[9];
    const float* root2 = (const float*)d_in[10];
    const float* b2    = (const float*)d_in[11];
    const float* cls_w = (const float*)d_in[12];
    const float* cls_b = (const float*)d_in[13];
    int E = in_sizes[1];
    float* out = (float*)d_out;

    void *pH0, *pH1, *pY1, *pS2, *pO2;
    cudaGetSymbolAddress(&pH0, g_h0);
    cudaGetSymbolAddress(&pH1, g_h1);
    cudaGetSymbolAddress(&pY1, g_y1);
    cudaGetSymbolAddress(&pS2, g_sum2);
    cudaGetSymbolAddress(&pO2, g_out2);

    size_t s2 = (size_t)NREPO * RREL * HDIM;  // 30,720,000

    // 1. zero counters + layer-2 sums
    zero_all_k<<<(unsigned)((s2 + 255) / 256), 256>>>();
    // 2. per-(dst, relation) edge counts for both layers
    count_k<<<(E + 255) / 256, 256>>>(er, ea, et, E);
    // 3. h0 = relu(x @ mlp_w + mlp_b)
    mlp_k<<<(NNODE * HDIM + 255) / 256, 256>>>(x, mlp_w, mlp_b);
    // 4. y1[repo, r] = h0[repo] @ W1[r]   (transform-before-aggregate)
    sgemm_k<<<dim3((NREPO + TM - 1) / TM, 1, RREL), 256>>>(
        (const float*)pH0, NREPO, HDIM, w1, (long)HDIM * HDIM,
        (float*)pY1, RREL * HDIM, HDIM, 0);
    // 5. h1 = h0 @ root1   (all N rows, overwrite)
    sgemm_k<<<dim3((NNODE + TM - 1) / TM, 1, 1), 256>>>(
        (const float*)pH0, NNODE, HDIM, root1, 0, (float*)pH1, HDIM, 0, 0);
    // 6. h1[actor] += y1[src,etype] / cnt1[actor,etype]   (per-edge scatter)
    scatter1_k<<<(E * 32 + 255) / 256, 256>>>(er, ea, et, E);
    // 7. h1 = relu(h1 + b1)
    finalize1_k<<<(NNODE * HDIM + 255) / 256, 256>>>(b1);
    // 8. sum2[repo,etype] += h1[actor]    (aggregate-before-transform)
    scatter2_k<<<(E * 32 + 255) / 256, 256>>>(er, ea, et, E);
    // 9. sum2 -> per-(repo,r) means
    scale2_k<<<(unsigned)((s2 + 255) / 256), 256>>>();
    // 10. out2 = h1[:30000] @ root2
    sgemm_k<<<dim3((NREPO + TM - 1) / TM, 1, 1), 256>>>(
        (const float*)pH1, NREPO, HDIM, root2, 0, (float*)pO2, HDIM, 0, 0);
    // 11. out2 += mean2.reshape(30000,1024) @ w2.reshape(1024,128)  (single GEMM)
    sgemm_k<<<dim3((NREPO + TM - 1) / TM, 1, 1), 256>>>(
        (const float*)pS2, NREPO, RREL * HDIM, w2, 0, (float*)pO2, HDIM, 0, 1);
    // 12. relu + bias + classifier
    fincls_k<<<NREPO, HDIM>>>(b2, cls_w, cls_b, out);
}

// round 2
// speedup vs baseline: 1.5634x; 1.5634x over previous
#include <cuda_runtime.h>
#include <cstdint>

#define NREPO 30000
#define NUSER 70000
#define NNODE 100000
#define RREL  8
#define HDIM  128
#define B1 (NUSER * RREL)   // 560000 layer-1 bins (actor,r)
#define B2 (NREPO * RREL)   // 240000 layer-2 bins (repo,r)
#define NB1 ((B1 + 1023) / 1024)
#define NB2 ((B2 + 1023) / 1024)
#define EMAX 1000000

// ---------------- scratch ----------------------------------------------------
__device__ float g_h0[(size_t)NREPO * HDIM];
__device__ float g_h1[(size_t)NNODE * HDIM];
__device__ float g_y1[(size_t)B2 * HDIM];
__device__ float g_sum2[(size_t)B2 * HDIM];
__device__ float g_out2[(size_t)NREPO * HDIM];
__device__ float g_uroot[HDIM];
__device__ int   g_cnt1[B1], g_off1[B1], g_cur1[B1], g_bsum1[NB1];
__device__ int   g_cnt2[B2], g_off2[B2], g_cur2[B2], g_bsum2[NB2];
__device__ int   g_perm1[EMAX];   // stores repo per edge, bucketed by (actor,r)
__device__ int   g_perm2[EMAX];   // stores actor per edge, bucketed by (repo,r)

// ---------------- counting / CSR build ---------------------------------------
__global__ void zero_cnt_k() {
    int i = blockIdx.x * blockDim.x + threadIdx.x;
    if (i < B1) g_cnt1[i] = 0;
    if (i < B2) g_cnt2[i] = 0;
}

__global__ void count_k(const int* __restrict__ er, const int* __restrict__ ea,
                        const int* __restrict__ et, int E) {
    int e = blockIdx.x * blockDim.x + threadIdx.x;
    if (e >= E) return;
    atomicAdd(&g_cnt1[ea[e] * RREL + et[e]], 1);
    atomicAdd(&g_cnt2[er[e] * RREL + et[e]], 1);
}

// per-block exclusive scan (1024 elems/block); bsum gets block totals
__global__ void scan_blk_k(const int* __restrict__ cnt, int n, int* __restrict__ off,
                           int* __restrict__ bsum) {
    __shared__ int s[1024];
    int t = threadIdx.x;
    int i = blockIdx.x * 1024 + t;
    int v = (i < n) ? cnt[i] : 0;
    s[t] = v;
    __syncthreads();
#pragma unroll
    for (int d = 1; d < 1024; d <<= 1) {
        int u = (t >= d) ? s[t - d] : 0;
        __syncthreads();
        s[t] += u;
        __syncthreads();
    }
    if (i < n) off[i] = s[t] - v;
    if (t == 1023) bsum[blockIdx.x] = s[1023];
}

__global__ void scan_top_k(int* __restrict__ bsum, int n) {
    __shared__ int s[1024];
    int t = threadIdx.x;
    int v = (t < n) ? bsum[t] : 0;
    s[t] = v;
    __syncthreads();
#pragma unroll
    for (int d = 1; d < 1024; d <<= 1) {
        int u = (t >= d) ? s[t - d] : 0;
        __syncthreads();
        s[t] += u;
        __syncthreads();
    }
    if (t < n) bsum[t] = s[t] - v;
}

__global__ void scan_add_k(int* __restrict__ off, const int* __restrict__ bsum,
                           int* __restrict__ cur, int n) {
    int i = blockIdx.x * blockDim.x + threadIdx.x;
    if (i >= n) return;
    int o = off[i] + bsum[i >> 10];
    off[i] = o;
    cur[i] = o;
}

__global__ void place_k(const int* __restrict__ er, const int* __restrict__ ea,
                        const int* __restrict__ et, int E) {
    int e = blockIdx.x * blockDim.x + threadIdx.x;
    if (e >= E) return;
    int repo = er[e], actor = ea[e], t = et[e];
    int p1 = atomicAdd(&g_cur1[actor * RREL + t], 1);
    g_perm1[p1] = repo;
    int p2 = atomicAdd(&g_cur2[repo * RREL + t], 1);
    g_perm2[p2] = actor;
}

// ---------------- dense pieces -----------------------------------------------
__global__ void mlp_k(const float* __restrict__ x, const float* __restrict__ w,
                      const float* __restrict__ b) {
    int g = blockIdx.x * blockDim.x + threadIdx.x;
    if (g >= NREPO * HDIM) return;
    int n = g >> 7, o = g & 127;
    float acc = b[o];
#pragma unroll
    for (int k = 0; k < 8; k++) acc = fmaf(__ldg(&x[n * 8 + k]), __ldg(&w[k * HDIM + o]), acc);
    g_h0[g] = fmaxf(acc, 0.f);
}

// user root term: relu(mlp_b) @ root1  (all user rows of h0 are identical)
__global__ void uroot_k(const float* __restrict__ mlp_b, const float* __restrict__ root1) {
    int o = threadIdx.x;
    float acc = 0.f;
#pragma unroll 8
    for (int k = 0; k < HDIM; k++)
        acc = fmaf(fmaxf(mlp_b[k], 0.f), root1[k * HDIM + o], acc);
    g_uroot[o] = acc;
}

// relu(bias+) for repo rows of h1 (actor rows handled inside agg1)
__global__ void fin_repo_k(const float* __restrict__ b1) {
    int g = blockIdx.x * blockDim.x + threadIdx.x;
    if (g >= NREPO * HDIM) return;
    g_h1[g] = fmaxf(g_h1[g] + b1[g & 127], 0.f);
}

// layer-1 aggregation: one warp per actor; gathers y1 rows per relation,
// applies 1/cnt, adds shared user root term + bias, relu, plain store.
__global__ void agg1_k(const float* __restrict__ b1) {
    int w = (blockIdx.x * blockDim.x + threadIdx.x) >> 5;
    int lane = threadIdx.x & 31;
    if (w >= NUSER) return;
    float4 acc = *(const float4*)(g_uroot + lane * 4);
#pragma unroll
    for (int r = 0; r < RREL; r++) {
        int bin = w * RREL + r;
        int deg = g_cnt1[bin];
        if (deg == 0) continue;
        int start = g_off1[bin];
        float4 s = make_float4(0.f, 0.f, 0.f, 0.f);
        for (int j = 0; j < deg; j++) {
            int repo = __ldg(g_perm1 + start + j);
            const float4 v = *(const float4*)(g_y1 + (((size_t)repo * RREL + r) << 7) + lane * 4);
            s.x += v.x; s.y += v.y; s.z += v.z; s.w += v.w;
        }
        float inv = 1.0f / (float)deg;
        acc.x = fmaf(s.x, inv, acc.x); acc.y = fmaf(s.y, inv, acc.y);
        acc.z = fmaf(s.z, inv, acc.z); acc.w = fmaf(s.w, inv, acc.w);
    }
    const float4 bb = *(const float4*)(b1 + lane * 4);
    acc.x = fmaxf(acc.x + bb.x, 0.f); acc.y = fmaxf(acc.y + bb.y, 0.f);
    acc.z = fmaxf(acc.z + bb.z, 0.f); acc.w = fmaxf(acc.w + bb.w, 0.f);
    *(float4*)(g_h1 + (((size_t)(NREPO + w)) << 7) + lane * 4) = acc;
}

// layer-2 aggregation: one warp per repo; for each relation compute the mean of
// h1[actor] rows (36MB region, L2-resident), plain store into sum2.
__global__ void agg2_k() {
    int w = (blockIdx.x * blockDim.x + threadIdx.x) >> 5;
    int lane = threadIdx.x & 31;
    if (w >= NREPO) return;
#pragma unroll
    for (int r = 0; r < RREL; r++) {
        int bin = w * RREL + r;
        int deg = g_cnt2[bin];
        float4 s = make_float4(0.f, 0.f, 0.f, 0.f);
        int start = g_off2[bin];
        for (int j = 0; j < deg; j++) {
            int actor = __ldg(g_perm2 + start + j);
            const float4 v = *(const float4*)(g_h1 + (((size_t)(NREPO + actor)) << 7) + lane * 4);
            s.x += v.x; s.y += v.y; s.z += v.z; s.w += v.w;
        }
        float inv = (deg > 0) ? 1.0f / (float)deg : 0.f;
        s.x *= inv; s.y *= inv; s.z *= inv; s.w *= inv;
        *(float4*)(g_sum2 + ((size_t)bin << 7) + lane * 4) = s;
    }
}

// finalize layer 2 + classifier
__global__ void fincls_k(const float* __restrict__ b2, const float* __restrict__ clsw,
                         const float* __restrict__ clsb, float* __restrict__ out) {
    int j = blockIdx.x;
    int t = threadIdx.x;
    float v = fmaxf(g_out2[(size_t)j * HDIM + t] + b2[t], 0.f);
    float p0 = v * clsw[t * 2 + 0];
    float p1 = v * clsw[t * 2 + 1];
#pragma unroll
    for (int o = 16; o; o >>= 1) {
        p0 += __shfl_xor_sync(0xffffffffu, p0, o);
        p1 += __shfl_xor_sync(0xffffffffu, p1, o);
    }
    __shared__ float s0[4], s1[4];
    if ((t & 31) == 0) { s0[t >> 5] = p0; s1[t >> 5] = p1; }
    __syncthreads();
    if (t == 0) {
        out[j * 2 + 0] = s0[0] + s0[1] + s0[2] + s0[3] + clsb[0];
        out[j * 2 + 1] = s1[0] + s1[1] + s1[2] + s1[3] + clsb[1];
    }
}

// ---------------- SGEMM: C[M x 128] = A[M x K(lda)] @ B[K x 128] -------------
// z: B += z*bStrideZ, A col offset += z*aOffZ, C col offset += z*cOffZ.
// mode: 0 = store, 2 = red.global.add (for K-split accumulation).
#define TM 128
#define TN 128
#define TK 16

__device__ __forceinline__ void red_add_v4(float* p, float a, float b, float c, float d) {
    asm volatile("red.global.add.v4.f32 [%0], {%1,%2,%3,%4};"
                 :: "l"(p), "f"(a), "f"(b), "f"(c), "f"(d) : "memory");
}

__global__ void __launch_bounds__(256)
sgemm_k(const float* __restrict__ A, int M, int K, int lda, int aOffZ,
        const float* __restrict__ B, long bStrideZ,
        float* __restrict__ C, int cstride, int cOffZ, int mode) {
    __shared__ float As[2][TK][TM];
    __shared__ float Bs[2][TK][TN];

    int z = blockIdx.z;
    B += (size_t)z * bStrideZ;
    const float* Abase = A + (size_t)z * aOffZ;
    int cOff = z * cOffZ;
    int m0 = blockIdx.x * TM;
    int tid = threadIdx.x;
    int tx = tid & 15, ty = tid >> 4;

    float acc[8][8];
#pragma unroll
    for (int i = 0; i < 8; i++)
#pragma unroll
        for (int j = 0; j < 8; j++) acc[i][j] = 0.f;

    auto loadA = [&](int k0, int buf) {
#pragma unroll
        for (int i = 0; i < 2; i++) {
            int q = tid + i * 256;
            int row = q >> 2;
            int kq = (q & 3) * 4;
            float4 v = make_float4(0.f, 0.f, 0.f, 0.f);
            int gm = m0 + row;
            if (gm < M) v = *(const float4*)(Abase + (size_t)gm * lda + k0 + kq);
            As[buf][kq + 0][row] = v.x;
            As[buf][kq + 1][row] = v.y;
            As[buf][kq + 2][row] = v.z;
            As[buf][kq + 3][row] = v.w;
        }
    };
    auto loadB = [&](int k0, int buf) {
#pragma unroll
        for (int i = 0; i < 2; i++) {
            int q = tid + i * 256;
            int kk = q >> 5;
            int n4 = (q & 31) * 4;
            *(float4*)&Bs[buf][kk][n4] = *(const float4*)(B + (size_t)(k0 + kk) * TN + n4);
        }
    };

    loadA(0, 0);
    loadB(0, 0);
    __syncthreads();
    int nk = K / TK;
    for (int kt = 0; kt < nk; kt++) {
        int buf = kt & 1;
        if (kt + 1 < nk) { loadA((kt + 1) * TK, buf ^ 1); loadB((kt + 1) * TK, buf ^ 1); }
#pragma unroll
        for (int kk = 0; kk < TK; kk++) {
            float a[8], b[8];
            *(float4*)&a[0] = *(const float4*)&As[buf][kk][ty * 8];
            *(float4*)&a[4] = *(const float4*)&As[buf][kk][ty * 8 + 4];
            *(float4*)&b[0] = *(const float4*)&Bs[buf][kk][tx * 8];
            *(float4*)&b[4] = *(const float4*)&Bs[buf][kk][tx * 8 + 4];
#pragma unroll
            for (int i = 0; i < 8; i++)
#pragma unroll
                for (int j = 0; j < 8; j++) acc[i][j] = fmaf(a[i], b[j], acc[i][j]);
        }
        __syncthreads();
    }

#pragma unroll
    for (int i = 0; i < 8; i++) {
        int gm = m0 + ty * 8 + i;
        if (gm >= M) continue;
        float* crow = C + (size_t)gm * cstride + cOff + tx * 8;
        if (mode == 2) {
            red_add_v4(crow + 0, acc[i][0], acc[i][1], acc[i][2], acc[i][3]);
            red_add_v4(crow + 4, acc[i][4], acc[i][5], acc[i][6], acc[i][7]);
        } else {
#pragma unroll
            for (int j = 0; j < 8; j++) crow[j] = acc[i][j];
        }
    }
}

// ---------------- driver -----------------------------------------------------
extern "C" void kernel_launch(void* const* d_in, const int* in_sizes, int n_in,
                              void* d_out, int out_size) {
    const float* x     = (const float*)d_in[0];
    const int*   er    = (const int*)d_in[1];
    const int*   ea    = (const int*)d_in[2];
    const int*   et    = (const int*)d_in[3];
    const float* mlp_w = (const float*)d_in[4];
    const float* mlp_b = (const float*)d_in[5];
    const float* w1    = (const float*)d_in[6];
    const float* root1 = (const float*)d_in[7];
    const float* b1    = (const float*)d_in[8];
    const float* w2    = (const float*)d_in[9];
    const float* root2 = (const float*)d_in[10];
    const float* b2    = (const float*)d_in[11];
    const float* cls_w = (const float*)d_in[12];
    const float* cls_b = (const float*)d_in[13];
    int E = in_sizes[1];
    float* out = (float*)d_out;

    void *pH0, *pH1, *pS2, *pO2, *pY1, *pOff1, *pOff2, *pBs1, *pBs2, *pCnt1, *pCnt2, *pCur1, *pCur2;
    cudaGetSymbolAddress(&pH0, g_h0);
    cudaGetSymbolAddress(&pH1, g_h1);
    cudaGetSymbolAddress(&pY1, g_y1);
    cudaGetSymbolAddress(&pS2, g_sum2);
    cudaGetSymbolAddress(&pO2, g_out2);
    cudaGetSymbolAddress(&pCnt1, g_cnt1);
    cudaGetSymbolAddress(&pCnt2, g_cnt2);
    cudaGetSymbolAddress(&pOff1, g_off1);
    cudaGetSymbolAddress(&pOff2, g_off2);
    cudaGetSymbolAddress(&pCur1, g_cur1);
    cudaGetSymbolAddress(&pCur2, g_cur2);
    cudaGetSymbolAddress(&pBs1, g_bsum1);
    cudaGetSymbolAddress(&pBs2, g_bsum2);

    // --- CSR construction (both layers) ---
    zero_cnt_k<<<(B1 + 255) / 256, 256>>>();
    count_k<<<(E + 255) / 256, 256>>>(er, ea, et, E);
    scan_blk_k<<<NB1, 1024>>>((const int*)pCnt1, B1, (int*)pOff1, (int*)pBs1);
    scan_blk_k<<<NB2, 1024>>>((const int*)pCnt2, B2, (int*)pOff2, (int*)pBs2);
    scan_top_k<<<1, 1024>>>((int*)pBs1, NB1);
    scan_top_k<<<1, 1024>>>((int*)pBs2, NB2);
    scan_add_k<<<(B1 + 255) / 256, 256>>>((int*)pOff1, (const int*)pBs1, (int*)pCur1, B1);
    scan_add_k<<<(B2 + 255) / 256, 256>>>((int*)pOff2, (const int*)pBs2, (int*)pCur2, B2);
    place_k<<<(E + 255) / 256, 256>>>(er, ea, et, E);

    // --- dense front ---
    mlp_k<<<(NREPO * HDIM + 255) / 256, 256>>>(x, mlp_w, mlp_b);
    uroot_k<<<1, HDIM>>>(mlp_b, root1);

    // y1[repo,r] = h0[repo] @ W1[r]
    sgemm_k<<<dim3((NREPO + TM - 1) / TM, 1, RREL), 256>>>(
        (const float*)pH0, NREPO, HDIM, HDIM, 0, w1, (long)HDIM * HDIM,
        (float*)pY1, RREL * HDIM, HDIM, 0);
    // h1[repo] = h0[repo] @ root1
    sgemm_k<<<dim3((NREPO + TM - 1) / TM, 1, 1), 256>>>(
        (const float*)pH0, NREPO, HDIM, HDIM, 0, root1, 0, (float*)pH1, HDIM, 0, 0);

    // layer-1 aggregation (writes actor rows of h1, fused bias+relu)
    agg1_k<<<(NUSER + 7) / 8, 256>>>(b1);
    // repo rows bias+relu
    fin_repo_k<<<(NREPO * HDIM + 255) / 256, 256>>>(b1);

    // layer-2 aggregation -> per-(repo,r) means
    agg2_k<<<(NREPO + 7) / 8, 256>>>();

    // out2 = h1[:NREPO] @ root2
    sgemm_k<<<dim3((NREPO + TM - 1) / TM, 1, 1), 256>>>(
        (const float*)pH1, NREPO, HDIM, HDIM, 0, root2, 0, (float*)pO2, HDIM, 0, 0);
    // out2 += mean2 @ w2  (K=1024 split into 8 chunks of 128, red.add epilogue)
    sgemm_k<<<dim3((NREPO + TM - 1) / TM, 1, RREL), 256>>>(
        (const float*)pS2, NREPO, HDIM, RREL * HDIM, HDIM, w2, (long)HDIM * HDIM,
        (float*)pO2, HDIM, 0, 2);

    // relu + bias + classifier
    fincls_k<<<NREPO, HDIM>>>(b2, cls_w, cls_b, out);
}